// round 1
// baseline (speedup 1.0000x reference)
#include <cuda_runtime.h>
#include <cuda_bf16.h>
#include <math.h>

// Problem constants
#define BATCH   2048            // windows
#define NTOK    49              // tokens per window
#define DIM     256
#define HEADS   8
#define HDIM    32
#define NW      64              // mask windows
#define M_ROWS  (BATCH * NTOK)  // 100352

// Scratch (allocation-free rule: __device__ globals)
__device__ float g_qkv[(size_t)BATCH * NTOK * 3 * DIM];   // [B,N,768]
__device__ float g_att[(size_t)BATCH * NTOK * DIM];       // [B,N,256]

// ---------------------------------------------------------------------------
// SGEMM: C[M,N] = A[M,K] * B[K,N] + bias[N]
// 128x128 tile, BK=8, 256 threads, 8x8 per-thread microtile.
// Requires M%128==0, N%128==0, K%8==0 (true for all our shapes).
// ---------------------------------------------------------------------------
__global__ void __launch_bounds__(256)
sgemm_bias(const float* __restrict__ A, const float* __restrict__ B,
           const float* __restrict__ bias, float* __restrict__ C,
           int M, int N, int K)
{
    __shared__ float As[8][128];
    __shared__ float Bs[8][128];

    const int tid  = threadIdx.x;
    const int tx   = tid & 15;        // 0..15 -> col group
    const int ty   = tid >> 4;        // 0..15 -> row group
    const int arow = tid >> 1;        // 0..127
    const int acol = (tid & 1) * 4;   // 0 or 4
    const int brow = tid >> 5;        // 0..7
    const int bcol = (tid & 31) * 4;  // 0..124

    const float* Ap = A + (size_t)(blockIdx.y * 128 + arow) * K + acol;
    const float* Bp = B + (size_t)brow * N + blockIdx.x * 128 + bcol;

    float acc[8][8];
#pragma unroll
    for (int i = 0; i < 8; ++i)
#pragma unroll
        for (int j = 0; j < 8; ++j) acc[i][j] = 0.f;

    const int nk = K >> 3;
    float4 av = *(const float4*)Ap;
    float4 bv = *(const float4*)Bp;

    for (int t = 0; t < nk; ++t) {
        As[acol + 0][arow] = av.x;
        As[acol + 1][arow] = av.y;
        As[acol + 2][arow] = av.z;
        As[acol + 3][arow] = av.w;
        *(float4*)&Bs[brow][bcol] = bv;
        __syncthreads();

        if (t + 1 < nk) {
            av = *(const float4*)(Ap + (t + 1) * 8);
            bv = *(const float4*)(Bp + (size_t)(t + 1) * 8 * N);
        }

#pragma unroll
        for (int k = 0; k < 8; ++k) {
            float4 a0 = *(const float4*)&As[k][ty * 4];
            float4 a1 = *(const float4*)&As[k][64 + ty * 4];
            float4 b0 = *(const float4*)&Bs[k][tx * 4];
            float4 b1 = *(const float4*)&Bs[k][64 + tx * 4];
            float ar[8] = {a0.x, a0.y, a0.z, a0.w, a1.x, a1.y, a1.z, a1.w};
            float br[8] = {b0.x, b0.y, b0.z, b0.w, b1.x, b1.y, b1.z, b1.w};
#pragma unroll
            for (int i = 0; i < 8; ++i)
#pragma unroll
                for (int j = 0; j < 8; ++j)
                    acc[i][j] = fmaf(ar[i], br[j], acc[i][j]);
        }
        __syncthreads();
    }

    // Epilogue with bias
    const int ccol0 = blockIdx.x * 128 + tx * 4;
    const int crow0 = blockIdx.y * 128 + ty * 4;
    float4 bias0 = *(const float4*)&bias[ccol0];
    float4 bias1 = *(const float4*)&bias[ccol0 + 64];

#pragma unroll
    for (int i = 0; i < 8; ++i) {
        int row = crow0 + ((i < 4) ? i : (60 + i));   // i>=4 -> +64+(i-4)
        float4 v0 = make_float4(acc[i][0] + bias0.x, acc[i][1] + bias0.y,
                                acc[i][2] + bias0.z, acc[i][3] + bias0.w);
        float4 v1 = make_float4(acc[i][4] + bias1.x, acc[i][5] + bias1.y,
                                acc[i][6] + bias1.z, acc[i][7] + bias1.w);
        *(float4*)&C[(size_t)row * N + ccol0]      = v0;
        *(float4*)&C[(size_t)row * N + ccol0 + 64] = v1;
    }
}

// ---------------------------------------------------------------------------
// Attention: one CTA per (b, h); 64 threads; thread r<49 owns output row r.
//   S = (q*scale) k^T + bias[h] + mask[b%64]; softmax rows; O = P v
// Writes g_att[b][n][h*32 + d]  (head-concatenated layout for proj GEMM).
// ---------------------------------------------------------------------------
__global__ void __launch_bounds__(64)
attn_kernel(const float* __restrict__ qkv, const float* __restrict__ mask,
            const float* __restrict__ bias_table, const int* __restrict__ rel_index,
            float* __restrict__ att)
{
    const int b = blockIdx.x;
    const int h = blockIdx.y;
    const int w = b & (NW - 1);
    const int r = threadIdx.x;

    __shared__ float sk[NTOK][HDIM];
    __shared__ float sv[NTOK][HDIM];

    // Stage K and V for this (b,h): coalesced within each token row
    const float* base = qkv + (size_t)b * NTOK * 3 * DIM;
    for (int idx = threadIdx.x; idx < NTOK * HDIM; idx += 64) {
        int n = idx >> 5, d = idx & 31;
        sk[n][d] = base[(size_t)n * 3 * DIM + DIM     + h * HDIM + d];
        sv[n][d] = base[(size_t)n * 3 * DIM + 2 * DIM + h * HDIM + d];
    }
    __syncthreads();

    if (r < NTOK) {
        const float scale = 0.17677669529663687f;  // 32^-0.5
        // q row (scaled) in registers
        float4 qv[8];
        const float4* qp = (const float4*)(base + (size_t)r * 3 * DIM + h * HDIM);
#pragma unroll
        for (int t = 0; t < 8; ++t) {
            float4 q = qp[t];
            qv[t] = make_float4(q.x * scale, q.y * scale, q.z * scale, q.w * scale);
        }

        const float* mrow = mask + ((size_t)w * NTOK + r) * NTOK;
        const int*   rrow = rel_index + r * NTOK;

        float s[NTOK];
        float mx = -1e30f;
#pragma unroll
        for (int j = 0; j < NTOK; ++j) {
            const float4* kp = (const float4*)sk[j];
            float a = 0.f;
#pragma unroll
            for (int t = 0; t < 8; ++t) {
                float4 kvv = kp[t];
                a = fmaf(qv[t].x, kvv.x, a);
                a = fmaf(qv[t].y, kvv.y, a);
                a = fmaf(qv[t].z, kvv.z, a);
                a = fmaf(qv[t].w, kvv.w, a);
            }
            a += bias_table[rrow[j] * HEADS + h] + mrow[j];
            s[j] = a;
            mx = fmaxf(mx, a);
        }

        float sum = 0.f;
#pragma unroll
        for (int j = 0; j < NTOK; ++j) {
            float e = __expf(s[j] - mx);
            s[j] = e;
            sum += e;
        }
        const float inv = 1.0f / sum;

        float4 o[8];
#pragma unroll
        for (int t = 0; t < 8; ++t) o[t] = make_float4(0.f, 0.f, 0.f, 0.f);
#pragma unroll
        for (int j = 0; j < NTOK; ++j) {
            float p = s[j] * inv;
            const float4* vp = (const float4*)sv[j];
#pragma unroll
            for (int t = 0; t < 8; ++t) {
                float4 vv = vp[t];
                o[t].x = fmaf(p, vv.x, o[t].x);
                o[t].y = fmaf(p, vv.y, o[t].y);
                o[t].z = fmaf(p, vv.z, o[t].z);
                o[t].w = fmaf(p, vv.w, o[t].w);
            }
        }

        float4* op = (float4*)(att + ((size_t)b * NTOK + r) * DIM + h * HDIM);
#pragma unroll
        for (int t = 0; t < 8; ++t) op[t] = o[t];
    }
}

// ---------------------------------------------------------------------------
extern "C" void kernel_launch(void* const* d_in, const int* in_sizes, int n_in,
                              void* d_out, int out_size)
{
    const float* x          = (const float*)d_in[0];
    const float* mask       = (const float*)d_in[1];
    const float* qkv_w      = (const float*)d_in[2];
    const float* qkv_b      = (const float*)d_in[3];
    const float* proj_w     = (const float*)d_in[4];
    const float* proj_b     = (const float*)d_in[5];
    const float* bias_table = (const float*)d_in[6];
    const int*   rel_index  = (const int*)d_in[7];
    float*       out        = (float*)d_out;

    void* p0; cudaGetSymbolAddress(&p0, g_qkv);
    void* p1; cudaGetSymbolAddress(&p1, g_att);
    float* qkv_buf = (float*)p0;
    float* att_buf = (float*)p1;

    // 1) QKV projection: [100352,256] x [256,768] + b
    {
        dim3 grid(768 / 128, M_ROWS / 128);
        sgemm_bias<<<grid, 256>>>(x, qkv_w, qkv_b, qkv_buf, M_ROWS, 3 * DIM, DIM);
    }
    // 2) Windowed attention per (b, h)
    {
        dim3 grid(BATCH, HEADS);
        attn_kernel<<<grid, 64>>>(qkv_buf, mask, bias_table, rel_index, att_buf);
    }
    // 3) Output projection: [100352,256] x [256,256] + b
    {
        dim3 grid(DIM / 128, M_ROWS / 128);
        sgemm_bias<<<grid, 256>>>(att_buf, proj_w, proj_b, out, M_ROWS, DIM, DIM);
    }
}

// round 3
// speedup vs baseline: 2.2740x; 2.2740x over previous
#include <cuda_runtime.h>
#include <cuda_bf16.h>
#include <cstdint>
#include <math.h>

// ---------------------------------------------------------------------------
// Problem constants
// ---------------------------------------------------------------------------
#define BATCH   2048
#define NTOK    49
#define DIM     256
#define HEADS   8
#define HDIM    32
#define NW      64
#define M_ROWS  (BATCH * NTOK)   // 100352
#define KTOT    256

// ---------------------------------------------------------------------------
// Scratch (__device__ globals: allocation-free rule)
// ---------------------------------------------------------------------------
__device__ float          g_qkv[(size_t)M_ROWS * 3 * DIM];   // fp32 [M,768]
__device__ __nv_bfloat16  g_x_h[(size_t)M_ROWS * DIM];       // x hi  [M,256]
__device__ __nv_bfloat16  g_x_l[(size_t)M_ROWS * DIM];       // x lo
__device__ __nv_bfloat16  g_att_h[(size_t)M_ROWS * DIM];     // O hi  [M,256]
__device__ __nv_bfloat16  g_att_l[(size_t)M_ROWS * DIM];     // O lo
__device__ __nv_bfloat16  g_wqkvT_h[3 * DIM * DIM];          // [768,256] (N,K)
__device__ __nv_bfloat16  g_wqkvT_l[3 * DIM * DIM];
__device__ __nv_bfloat16  g_wprojT_h[DIM * DIM];             // [256,256]
__device__ __nv_bfloat16  g_wprojT_l[DIM * DIM];

// ---------------------------------------------------------------------------
// Helpers
// ---------------------------------------------------------------------------
__device__ __forceinline__ uint32_t smem_to_u32(const void* p) {
    uint32_t a;
    asm("{ .reg .u64 t; cvta.to.shared.u64 t, %1; cvt.u32.u64 %0, t; }" : "=r"(a) : "l"(p));
    return a;
}
__device__ __forceinline__ uint32_t pack_bf2(__nv_bfloat16 a, __nv_bfloat16 b) {
    __nv_bfloat162 t = __halves2bfloat162(a, b);
    return *reinterpret_cast<uint32_t*>(&t);
}
__device__ __forceinline__ void mma16816(float* c, const uint32_t* a, const uint32_t* b) {
    asm volatile(
        "mma.sync.aligned.m16n8k16.row.col.f32.bf16.bf16.f32 "
        "{%0,%1,%2,%3}, {%4,%5,%6,%7}, {%8,%9}, {%0,%1,%2,%3};"
        : "+f"(c[0]), "+f"(c[1]), "+f"(c[2]), "+f"(c[3])
        : "r"(a[0]), "r"(a[1]), "r"(a[2]), "r"(a[3]), "r"(b[0]), "r"(b[1]));
}
#define CP_ASYNC16(dst_u32, src_ptr) \
    asm volatile("cp.async.cg.shared.global [%0], [%1], 16;" :: "r"(dst_u32), "l"(src_ptr))
#define CP_COMMIT() asm volatile("cp.async.commit_group;" ::: "memory")

// ---------------------------------------------------------------------------
// split x: fp32 -> bf16 hi/lo
// ---------------------------------------------------------------------------
__global__ void split_x(const float* __restrict__ x, __nv_bfloat16* __restrict__ xh,
                        __nv_bfloat16* __restrict__ xl, int n4)
{
    int i = blockIdx.x * blockDim.x + threadIdx.x;
    if (i >= n4) return;
    float4 v = ((const float4*)x)[i];
    __nv_bfloat16 hx = __float2bfloat16(v.x), hy = __float2bfloat16(v.y);
    __nv_bfloat16 hz = __float2bfloat16(v.z), hw = __float2bfloat16(v.w);
    uint2 hv = make_uint2(pack_bf2(hx, hy), pack_bf2(hz, hw));
    uint2 lv = make_uint2(
        pack_bf2(__float2bfloat16(v.x - __bfloat162float(hx)),
                 __float2bfloat16(v.y - __bfloat162float(hy))),
        pack_bf2(__float2bfloat16(v.z - __bfloat162float(hz)),
                 __float2bfloat16(v.w - __bfloat162float(hw))));
    ((uint2*)xh)[i] = hv;
    ((uint2*)xl)[i] = lv;
}

// weight transpose + split: w[K,N] -> wT hi/lo [N,K]
__global__ void convert_wT(const float* __restrict__ w, __nv_bfloat16* __restrict__ bh,
                           __nv_bfloat16* __restrict__ bl, int K, int N)
{
    int idx = blockIdx.x * blockDim.x + threadIdx.x;
    if (idx >= K * N) return;
    int k = idx / N, n = idx % N;
    float v = w[idx];
    __nv_bfloat16 h = __float2bfloat16(v);
    bh[(size_t)n * K + k] = h;
    bl[(size_t)n * K + k] = __float2bfloat16(v - __bfloat162float(h));
}

// ---------------------------------------------------------------------------
// mma.sync split-bf16 GEMM:
//   C[M,NFULL] = (Ah+Al)[M,256] * (Bh+Bl)^T[NFULL,256] + bias   (3-product)
// CTA 128x128, BK=64, cp.async double-buffered, 256 threads (8 warps 4m x 2n).
// ---------------------------------------------------------------------------
#define BKC   64
#define LDSK  72                       // padded row (elements): 144B = 36 banks
#define ARRE  (128 * LDSK)             // 9216 elements per array
#define STAGE (4 * ARRE)               // Ah,Al,Bh,Bl
#define SMEM_GEMM_BYTES (2 * STAGE * 2)  // 147456

template<int NFULL>
__global__ void __launch_bounds__(256, 1)
gemm_mma(const __nv_bfloat16* __restrict__ Ah, const __nv_bfloat16* __restrict__ Al,
         const __nv_bfloat16* __restrict__ Bh, const __nv_bfloat16* __restrict__ Bl,
         const float* __restrict__ bias, float* __restrict__ C)
{
    extern __shared__ __nv_bfloat16 sm[];
    const uint32_t smb = smem_to_u32(sm);
    const int tid  = threadIdx.x;
    const int wid  = tid >> 5, lane = tid & 31;
    const int lq   = lane >> 2, lr = lane & 3;
    const int bm   = blockIdx.y, bn = blockIdx.x;
    const int wm   = (wid & 3) * 32;   // warp m offset
    const int wn   = (wid >> 2) * 64;  // warp n offset

    const __nv_bfloat16* base0 = Ah + (size_t)bm * 128 * KTOT;
    const __nv_bfloat16* base1 = Al + (size_t)bm * 128 * KTOT;
    const __nv_bfloat16* base2 = Bh + (size_t)bn * 128 * KTOT;
    const __nv_bfloat16* base3 = Bl + (size_t)bn * 128 * KTOT;

    float acc[2][8][4];
#pragma unroll
    for (int t = 0; t < 2; ++t)
#pragma unroll
        for (int j = 0; j < 8; ++j)
#pragma unroll
            for (int e = 0; e < 4; ++e) acc[t][j][e] = 0.f;

    const int NC = KTOT / BKC;   // 4

    auto load_stage = [&](int c, int s) {
        const __nv_bfloat16* bases[4] = {base0, base1, base2, base3};
        const uint32_t sb = smb + (uint32_t)s * STAGE * 2;
#pragma unroll
        for (int a = 0; a < 4; ++a) {
#pragma unroll
            for (int i2 = 0; i2 < 4; ++i2) {
                int rem = i2 * 256 + tid;        // 0..1023
                int row = rem >> 3, ch = rem & 7;
                const __nv_bfloat16* src = bases[a] + (size_t)row * KTOT + c * BKC + ch * 8;
                uint32_t dst = sb + (uint32_t)(a * ARRE + row * LDSK + ch * 8) * 2;
                CP_ASYNC16(dst, src);
            }
        }
        CP_COMMIT();
    };

    load_stage(0, 0);

    for (int c = 0; c < NC; ++c) {
        if (c + 1 < NC) {
            load_stage(c + 1, (c + 1) & 1);
            asm volatile("cp.async.wait_group 1;" ::: "memory");
        } else {
            asm volatile("cp.async.wait_group 0;" ::: "memory");
        }
        __syncthreads();

        const __nv_bfloat16* st = sm + (size_t)(c & 1) * STAGE;
        const __nv_bfloat16* sAh = st;
        const __nv_bfloat16* sAl = st + ARRE;
        const __nv_bfloat16* sBh = st + 2 * ARRE;
        const __nv_bfloat16* sBl = st + 3 * ARRE;

#pragma unroll
        for (int s16 = 0; s16 < BKC / 16; ++s16) {
            // A fragments (hi & lo) for 2 m-tiles
            uint32_t afh[2][4], afl[2][4];
#pragma unroll
            for (int t = 0; t < 2; ++t) {
                int r0 = wm + t * 16 + lq;
                int cc = s16 * 16 + lr * 2;
                const __nv_bfloat16* ph = sAh + r0 * LDSK + cc;
                const __nv_bfloat16* pl = sAl + r0 * LDSK + cc;
                afh[t][0] = *(const uint32_t*)(ph);
                afh[t][1] = *(const uint32_t*)(ph + 8 * LDSK);
                afh[t][2] = *(const uint32_t*)(ph + 8);
                afh[t][3] = *(const uint32_t*)(ph + 8 * LDSK + 8);
                afl[t][0] = *(const uint32_t*)(pl);
                afl[t][1] = *(const uint32_t*)(pl + 8 * LDSK);
                afl[t][2] = *(const uint32_t*)(pl + 8);
                afl[t][3] = *(const uint32_t*)(pl + 8 * LDSK + 8);
            }
#pragma unroll
            for (int j = 0; j < 8; ++j) {
                int n0 = wn + j * 8 + lq;
                int kk = s16 * 16 + lr * 2;
                const __nv_bfloat16* pbh = sBh + n0 * LDSK + kk;
                const __nv_bfloat16* pbl = sBl + n0 * LDSK + kk;
                uint32_t bh[2], bl[2];
                bh[0] = *(const uint32_t*)(pbh);
                bh[1] = *(const uint32_t*)(pbh + 8);
                bl[0] = *(const uint32_t*)(pbl);
                bl[1] = *(const uint32_t*)(pbl + 8);
#pragma unroll
                for (int t = 0; t < 2; ++t) {
                    mma16816(acc[t][j], afh[t], bh);   // AhBh
                    mma16816(acc[t][j], afh[t], bl);   // AhBl
                    mma16816(acc[t][j], afl[t], bh);   // AlBh
                }
            }
        }
        __syncthreads();
    }

    // Epilogue with bias
#pragma unroll
    for (int t = 0; t < 2; ++t) {
        int r0 = bm * 128 + wm + t * 16 + lq;
#pragma unroll
        for (int j = 0; j < 8; ++j) {
            int col = bn * 128 + wn + j * 8 + lr * 2;
            float b0 = bias[col], b1 = bias[col + 1];
            float2 v0 = make_float2(acc[t][j][0] + b0, acc[t][j][1] + b1);
            float2 v1 = make_float2(acc[t][j][2] + b0, acc[t][j][3] + b1);
            *(float2*)&C[(size_t)r0 * NFULL + col]       = v0;
            *(float2*)&C[(size_t)(r0 + 8) * NFULL + col] = v1;
        }
    }
}

// ---------------------------------------------------------------------------
// Attention: one CTA per (b, h); 64 threads; thread r<49 owns output row r.
// Writes hi/lo bf16 split of O (proj GEMM A operand).
// ---------------------------------------------------------------------------
__global__ void __launch_bounds__(64)
attn_kernel(const float* __restrict__ qkv, const float* __restrict__ mask,
            const float* __restrict__ bias_table, const int* __restrict__ rel_index,
            __nv_bfloat16* __restrict__ att_h, __nv_bfloat16* __restrict__ att_l)
{
    const int b = blockIdx.x;
    const int h = blockIdx.y;
    const int w = b & (NW - 1);
    const int r = threadIdx.x;

    __shared__ float sk[NTOK][HDIM];
    __shared__ float sv[NTOK][HDIM];

    const float* base = qkv + (size_t)b * NTOK * 3 * DIM;
    for (int idx = threadIdx.x; idx < NTOK * HDIM; idx += 64) {
        int n = idx >> 5, d = idx & 31;
        sk[n][d] = base[(size_t)n * 3 * DIM + DIM + h * HDIM + d];
        sv[n][d] = base[(size_t)n * 3 * DIM + 2 * DIM + h * HDIM + d];
    }
    __syncthreads();

    if (r < NTOK) {
        const float scale = 0.17677669529663687f;  // 32^-0.5
        float4 qv[8];
        const float4* qp = (const float4*)(base + (size_t)r * 3 * DIM + h * HDIM);
#pragma unroll
        for (int t = 0; t < 8; ++t) {
            float4 q = qp[t];
            qv[t] = make_float4(q.x * scale, q.y * scale, q.z * scale, q.w * scale);
        }

        const float* mrow = mask + ((size_t)w * NTOK + r) * NTOK;
        const int*   rrow = rel_index + r * NTOK;

        float s[NTOK];
        float mx = -1e30f;
#pragma unroll
        for (int j = 0; j < NTOK; ++j) {
            const float4* kp = (const float4*)sk[j];
            float a = 0.f;
#pragma unroll
            for (int t = 0; t < 8; ++t) {
                float4 kvv = kp[t];
                a = fmaf(qv[t].x, kvv.x, a);
                a = fmaf(qv[t].y, kvv.y, a);
                a = fmaf(qv[t].z, kvv.z, a);
                a = fmaf(qv[t].w, kvv.w, a);
            }
            a += bias_table[rrow[j] * HEADS + h] + mrow[j];
            s[j] = a;
            mx = fmaxf(mx, a);
        }

        float sum = 0.f;
#pragma unroll
        for (int j = 0; j < NTOK; ++j) {
            float e = __expf(s[j] - mx);
            s[j] = e;
            sum += e;
        }
        const float inv = 1.0f / sum;

        float4 o[8];
#pragma unroll
        for (int t = 0; t < 8; ++t) o[t] = make_float4(0.f, 0.f, 0.f, 0.f);
#pragma unroll
        for (int j = 0; j < NTOK; ++j) {
            float p = s[j] * inv;
            const float4* vp = (const float4*)sv[j];
#pragma unroll
            for (int t = 0; t < 8; ++t) {
                float4 vv = vp[t];
                o[t].x = fmaf(p, vv.x, o[t].x);
                o[t].y = fmaf(p, vv.y, o[t].y);
                o[t].z = fmaf(p, vv.z, o[t].z);
                o[t].w = fmaf(p, vv.w, o[t].w);
            }
        }

        const size_t eo = ((size_t)b * NTOK + r) * DIM + h * HDIM;
#pragma unroll
        for (int t = 0; t < 8; ++t) {
            float4 v = o[t];
            __nv_bfloat16 hx = __float2bfloat16(v.x), hy = __float2bfloat16(v.y);
            __nv_bfloat16 hz = __float2bfloat16(v.z), hw = __float2bfloat16(v.w);
            uint2 hv = make_uint2(pack_bf2(hx, hy), pack_bf2(hz, hw));
            uint2 lv = make_uint2(
                pack_bf2(__float2bfloat16(v.x - __bfloat162float(hx)),
                         __float2bfloat16(v.y - __bfloat162float(hy))),
                pack_bf2(__float2bfloat16(v.z - __bfloat162float(hz)),
                         __float2bfloat16(v.w - __bfloat162float(hw))));
            *(uint2*)(att_h + eo + t * 4) = hv;
            *(uint2*)(att_l + eo + t * 4) = lv;
        }
    }
}

// ---------------------------------------------------------------------------
extern "C" void kernel_launch(void* const* d_in, const int* in_sizes, int n_in,
                              void* d_out, int out_size)
{
    const float* x          = (const float*)d_in[0];
    const float* mask       = (const float*)d_in[1];
    const float* qkv_w      = (const float*)d_in[2];
    const float* qkv_b      = (const float*)d_in[3];
    const float* proj_w     = (const float*)d_in[4];
    const float* proj_b     = (const float*)d_in[5];
    const float* bias_table = (const float*)d_in[6];
    const int*   rel_index  = (const int*)d_in[7];
    float*       out        = (float*)d_out;

    void* p;
    cudaGetSymbolAddress(&p, g_qkv);     float* qkv_buf = (float*)p;
    cudaGetSymbolAddress(&p, g_x_h);     __nv_bfloat16* xh  = (__nv_bfloat16*)p;
    cudaGetSymbolAddress(&p, g_x_l);     __nv_bfloat16* xl  = (__nv_bfloat16*)p;
    cudaGetSymbolAddress(&p, g_att_h);   __nv_bfloat16* ath = (__nv_bfloat16*)p;
    cudaGetSymbolAddress(&p, g_att_l);   __nv_bfloat16* atl = (__nv_bfloat16*)p;
    cudaGetSymbolAddress(&p, g_wqkvT_h); __nv_bfloat16* wqh = (__nv_bfloat16*)p;
    cudaGetSymbolAddress(&p, g_wqkvT_l); __nv_bfloat16* wql = (__nv_bfloat16*)p;
    cudaGetSymbolAddress(&p, g_wprojT_h); __nv_bfloat16* wph = (__nv_bfloat16*)p;
    cudaGetSymbolAddress(&p, g_wprojT_l); __nv_bfloat16* wpl = (__nv_bfloat16*)p;

    static bool attr_done = false;
    if (!attr_done) {
        cudaFuncSetAttribute(gemm_mma<3 * DIM>,
                             cudaFuncAttributeMaxDynamicSharedMemorySize, SMEM_GEMM_BYTES);
        cudaFuncSetAttribute(gemm_mma<DIM>,
                             cudaFuncAttributeMaxDynamicSharedMemorySize, SMEM_GEMM_BYTES);
        attr_done = true;
    }

    // 0) operand prep
    split_x<<<(M_ROWS * DIM / 4 + 255) / 256, 256>>>(x, xh, xl, M_ROWS * DIM / 4);
    convert_wT<<<(3 * DIM * DIM + 255) / 256, 256>>>(qkv_w, wqh, wql, DIM, 3 * DIM);
    convert_wT<<<(DIM * DIM + 255) / 256, 256>>>(proj_w, wph, wpl, DIM, DIM);

    // 1) QKV projection: [100352,256] x [256,768] + b  -> fp32
    {
        dim3 grid(3 * DIM / 128, M_ROWS / 128);   // (6, 784)
        gemm_mma<3 * DIM><<<grid, 256, SMEM_GEMM_BYTES>>>(xh, xl, wqh, wql, qkv_b, qkv_buf);
    }
    // 2) Windowed attention
    {
        dim3 grid(BATCH, HEADS);
        attn_kernel<<<grid, 64>>>(qkv_buf, mask, bias_table, rel_index, ath, atl);
    }
    // 3) Output projection: [100352,256] x [256,256] + b -> out
    {
        dim3 grid(DIM / 128, M_ROWS / 128);       // (2, 784)
        gemm_mma<DIM><<<grid, 256, SMEM_GEMM_BYTES>>>(ath, atl, wph, wpl, proj_b, out);
    }
}